// round 1
// baseline (speedup 1.0000x reference)
#include <cuda_runtime.h>
#include <math.h>

#define NN 100000
#define NE 1600000
#define DD 128
#define KK 256      // concat(mean, x) inner dim
#define BM 64       // rows per block in gemm

// Scratch (device globals — no allocation allowed)
__device__ float g_agg[(size_t)NN * DD];   // 51.2 MB
__device__ float g_cnt[NN];
__device__ float g_sl[NN];
__device__ float g_pre[NN];
__device__ float g_t[NN];
__device__ int   g_is64;

// ---------------------------------------------------------------------------
// Detect edge_index dtype: jax may have emitted int32 (x64 disabled) or int64.
// For int64 values < 2^31, every odd 32-bit word is 0. 16 consecutive zeros in
// odd slots of a uniform-[0,100000) int32 array has probability ~1e-80.
__global__ void detect_kernel(const int* __restrict__ e) {
    if (threadIdx.x == 0) {
        int z = 0;
#pragma unroll
        for (int i = 1; i < 32; i += 2) z |= e[i];
        g_is64 = (z == 0) ? 1 : 0;
    }
}

__global__ void zero_kernel() {
    size_t idx = (size_t)blockIdx.x * blockDim.x + threadIdx.x;
    if (idx < (size_t)NN * DD) g_agg[idx] = 0.f;
    if (idx < NN) { g_cnt[idx] = 0.f; g_t[idx] = 0.f; }
}

// ---------------------------------------------------------------------------
// Layer-1 aggregation: one warp per edge; each lane moves 16B via vector RED.
__global__ void __launch_bounds__(256) edge_agg1_kernel(
    const int* __restrict__ e32, const long long* __restrict__ e64,
    const float* __restrict__ x) {
    unsigned tid  = blockIdx.x * 256u + threadIdx.x;
    unsigned e    = tid >> 5;
    if (e >= NE) return;
    unsigned lane = tid & 31;
    int src, dst;
    if (g_is64) {
        src = (int)__ldg(&e64[e]);
        dst = (int)__ldg(&e64[NE + e]);
    } else {
        src = __ldg(&e32[e]);
        dst = __ldg(&e32[NE + e]);
    }
    float4 v = __ldg((const float4*)(x + (size_t)src * DD) + lane);
    float* a = g_agg + (size_t)dst * DD + lane * 4;
    asm volatile("red.global.add.v4.f32 [%0], {%1,%2,%3,%4};"
                 :: "l"(a), "f"(v.x), "f"(v.y), "f"(v.z), "f"(v.w)
                 : "memory");
    if (lane == 0) atomicAdd(&g_cnt[dst], 1.0f);
}

// ---------------------------------------------------------------------------
// Fused layer-1 GEMM + epilogue:
//   h = [agg/cnt | x] @ [W1_l ; W1_r]^T + b1      (written to outh, pre-relu)
//   s_l = relu(h)·w2_l,  pre = relu(h)·w2_r + b2  (scalars for layer 2)
// Weights live in smem transposed ([k][c]) with a 4-float XOR swizzle so both
// the transposing store and the float4 compute loads avoid 32-way conflicts.
__global__ void __launch_bounds__(256, 1) sage1_kernel(
    const float* __restrict__ x,
    const float* __restrict__ w1l, const float* __restrict__ b1l,
    const float* __restrict__ w1r,
    const float* __restrict__ w2l, const float* __restrict__ b2l,
    const float* __restrict__ w2r,
    float* __restrict__ outh) {
    extern __shared__ float smem[];
    float* Ws = smem;                 // [256][128] swizzled
    float* Zs = smem + KK * DD;       // [64][256]
    int t  = threadIdx.x;
    int m0 = blockIdx.x * BM;

    // Load both weight matrices transposed + swizzled (coalesced global reads)
    for (int idx = t; idx < DD * DD; idx += 256) {
        int c = idx >> 7, k = idx & 127;
        int sc = c ^ ((k & 7) << 2);
        Ws[k * DD + sc]        = w1l[idx];   // w1l[c][k] -> Ws[k][c]
        Ws[(k + DD) * DD + sc] = w1r[idx];
    }
    // Load Z tile: first 128 k = mean (agg/cnt), next 128 = x
    for (int i = t; i < BM * KK; i += 256) {
        int r = i >> 8;
        int k = i & 255;
        int n = m0 + r;
        float v = 0.f;
        if (n < NN) {
            if (k < DD) {
                float cv = g_cnt[n];
                v = g_agg[(size_t)n * DD + k] * (1.f / fmaxf(cv, 1.f));
            } else {
                v = __ldg(&x[(size_t)n * DD + (k - DD)]);
            }
        }
        Zs[i] = v;
    }
    __syncthreads();

    int tx = t & 31, ty = t >> 5;     // warp = fixed ty (8 rows), lanes = cols
    int c0 = tx * 4;
    float acc[8][4];
#pragma unroll
    for (int i = 0; i < 8; i++) {
        acc[i][0] = 0.f; acc[i][1] = 0.f; acc[i][2] = 0.f; acc[i][3] = 0.f;
    }

    for (int k0 = 0; k0 < KK; k0 += 4) {
        float4 av[8];
#pragma unroll
        for (int i = 0; i < 8; i++)
            av[i] = *(const float4*)&Zs[(ty * 8 + i) * KK + k0];
#pragma unroll
        for (int kk = 0; kk < 4; kk++) {
            int k = k0 + kk;
            float4 b = *(const float4*)&Ws[k * DD + (c0 ^ ((k & 7) << 2))];
#pragma unroll
            for (int i = 0; i < 8; i++) {
                float ai = (&av[i].x)[kk];
                acc[i][0] = fmaf(ai, b.x, acc[i][0]);
                acc[i][1] = fmaf(ai, b.y, acc[i][1]);
                acc[i][2] = fmaf(ai, b.z, acc[i][2]);
                acc[i][3] = fmaf(ai, b.w, acc[i][3]);
            }
        }
    }

    // Epilogue: bias, write h, relu-project to layer-2 scalars
    float4 bb  = __ldg((const float4*)b1l + tx);
    float4 wl4 = __ldg((const float4*)w2l + tx);
    float4 wr4 = __ldg((const float4*)w2r + tx);
    float  b2  = __ldg(b2l);
#pragma unroll
    for (int i = 0; i < 8; i++) {
        int r = m0 + ty * 8 + i;
        float h0 = acc[i][0] + bb.x;
        float h1 = acc[i][1] + bb.y;
        float h2 = acc[i][2] + bb.z;
        float h3 = acc[i][3] + bb.w;
        float r0 = fmaxf(h0, 0.f), r1 = fmaxf(h1, 0.f);
        float r2 = fmaxf(h2, 0.f), r3 = fmaxf(h3, 0.f);
        float sl = r0 * wl4.x + r1 * wl4.y + r2 * wl4.z + r3 * wl4.w;
        float sr = r0 * wr4.x + r1 * wr4.y + r2 * wr4.z + r3 * wr4.w;
#pragma unroll
        for (int off = 16; off > 0; off >>= 1) {
            sl += __shfl_xor_sync(0xffffffffu, sl, off);
            sr += __shfl_xor_sync(0xffffffffu, sr, off);
        }
        if (r < NN) {
            *(float4*)&outh[(size_t)r * DD + c0] = make_float4(h0, h1, h2, h3);
            if (tx == 0) { g_sl[r] = sl; g_pre[r] = sr + b2; }
        }
    }
}

// ---------------------------------------------------------------------------
// Layer-2 aggregation collapsed to scalars: 1 float per edge.
__global__ void edge_agg2_kernel(const int* __restrict__ e32,
                                 const long long* __restrict__ e64) {
    unsigned e = blockIdx.x * 256u + threadIdx.x;
    if (e >= NE) return;
    int src, dst;
    if (g_is64) {
        src = (int)__ldg(&e64[e]);
        dst = (int)__ldg(&e64[NE + e]);
    } else {
        src = __ldg(&e32[e]);
        dst = __ldg(&e32[NE + e]);
    }
    atomicAdd(&g_t[dst], g_sl[src]);
}

__global__ void final_kernel(float* __restrict__ out0) {
    int i = blockIdx.x * 256 + threadIdx.x;
    if (i < NN) {
        float v = g_t[i] / fmaxf(g_cnt[i], 1.f) + g_pre[i];
        out0[i] = 1.f / (1.f + expf(-v));
    }
}

// ---------------------------------------------------------------------------
extern "C" void kernel_launch(void* const* d_in, const int* in_sizes, int n_in,
                              void* d_out, int out_size) {
    const float*     x   = (const float*)d_in[0];
    const int*       e32 = (const int*)d_in[1];
    const long long* e64 = (const long long*)d_in[1];
    const float*     w1l = (const float*)d_in[2];
    const float*     b1l = (const float*)d_in[3];
    const float*     w1r = (const float*)d_in[4];
    const float*     w2l = (const float*)d_in[5];
    const float*     b2l = (const float*)d_in[6];
    const float*     w2r = (const float*)d_in[7];
    float* out0 = (float*)d_out;       // out [N,1]
    float* outh = out0 + NN;           // h   [N,128]

    const int smem_bytes = (KK * DD + BM * KK) * (int)sizeof(float); // 192 KB
    cudaFuncSetAttribute(sage1_kernel,
                         cudaFuncAttributeMaxDynamicSharedMemorySize, smem_bytes);

    detect_kernel<<<1, 32>>>(e32);
    zero_kernel<<<(NN * DD) / 256, 256>>>();
    edge_agg1_kernel<<<(NE * 32) / 256, 256>>>(e32, e64, x);
    sage1_kernel<<<(NN + BM - 1) / BM, 256, smem_bytes>>>(
        x, w1l, b1l, w1r, w2l, b2l, w2r, outh);
    edge_agg2_kernel<<<(NE + 255) / 256, 256>>>(e32, e64);
    final_kernel<<<(NN + 255) / 256, 256>>>(out0);
}

// round 2
// speedup vs baseline: 1.6153x; 1.6153x over previous
#include <cuda_runtime.h>
#include <math.h>

#define NN 100000
#define NE 1600000
#define DD 128
#define KK 256      // concat(mean, x) inner dim
#define BM 128
#define BK 8

// Scratch (device globals — no allocation allowed)
__device__ float g_agg[(size_t)NN * DD];   // 51.2 MB
__device__ float g_cnt[NN];
__device__ float g_rcp[NN];
__device__ float g_sl[NN];
__device__ float g_pre[NN];
__device__ float g_t[NN];
__device__ float g_wt[KK * DD];            // transposed [k][n] weights
__device__ int   g_is64;

// ---------------------------------------------------------------------------
// Detect edge_index dtype (int32 vs int64): for int64 < 2^31 every odd 32-bit
// word is 0; 16 consecutive zeros in random int32 data has prob ~1e-80.
__global__ void detect_kernel(const int* __restrict__ e) {
    if (threadIdx.x == 0) {
        int z = 0;
#pragma unroll
        for (int i = 1; i < 32; i += 2) z |= e[i];
        g_is64 = (z == 0) ? 1 : 0;
    }
}

__global__ void zero_kernel() {
    size_t idx = (size_t)blockIdx.x * blockDim.x + threadIdx.x;
    if (idx < (size_t)NN * DD) g_agg[idx] = 0.f;
    if (idx < NN) { g_cnt[idx] = 0.f; g_t[idx] = 0.f; }
}

// Transpose+concat weights: g_wt[k][n] = (k<128 ? w1l[n][k] : w1r[n][k-128])
__global__ void trans_kernel(const float* __restrict__ w1l,
                             const float* __restrict__ w1r) {
    int idx = blockIdx.x * 256 + threadIdx.x;      // 0 .. 32767
    if (idx < KK * DD) {
        int k = idx >> 7, n = idx & 127;
        g_wt[idx] = (k < DD) ? w1l[n * DD + k] : w1r[n * DD + (k - DD)];
    }
}

__global__ void rcp_kernel() {
    int i = blockIdx.x * 256 + threadIdx.x;
    if (i < NN) g_rcp[i] = 1.f / fmaxf(g_cnt[i], 1.f);
}

// ---------------------------------------------------------------------------
// Layer-1 aggregation: one warp per edge; each lane moves 16B via vector RED.
__global__ void __launch_bounds__(256) edge_agg1_kernel(
    const int* __restrict__ e32, const long long* __restrict__ e64,
    const float* __restrict__ x) {
    unsigned tid  = blockIdx.x * 256u + threadIdx.x;
    unsigned e    = tid >> 5;
    if (e >= NE) return;
    unsigned lane = tid & 31;
    int src, dst;
    if (g_is64) {
        src = (int)__ldg(&e64[e]);
        dst = (int)__ldg(&e64[NE + e]);
    } else {
        src = __ldg(&e32[e]);
        dst = __ldg(&e32[NE + e]);
    }
    float4 v = __ldg((const float4*)(x + (size_t)src * DD) + lane);
    float* a = g_agg + (size_t)dst * DD + lane * 4;
    asm volatile("red.global.add.v4.f32 [%0], {%1,%2,%3,%4};"
                 :: "l"(a), "f"(v.x), "f"(v.y), "f"(v.z), "f"(v.w)
                 : "memory");
    if (lane == 0) atomicAdd(&g_cnt[dst], 1.0f);
}

// ---------------------------------------------------------------------------
// Layer-1 GEMM: h = [agg*rcp | x] (100k x 256) @ g_wt (256 x 128) + b1.
// Classic double-buffered SGEMM: BM=128, BN=128, BK=8, 256 thr, 8x8 microtile.
__global__ void __launch_bounds__(256, 2) sage1_kernel(
    const float* __restrict__ x, const float* __restrict__ b1l,
    float* __restrict__ outh) {
    __shared__ float As[2][BK][BM];
    __shared__ float Bs[2][BK][DD];

    const int tid = threadIdx.x;
    const int m0  = blockIdx.x * BM;
    const int tx  = tid & 15, ty = tid >> 4;

    // A-load mapping: one float4 per thread per stage
    const int arow = tid >> 1;            // 0..127
    const int akq  = (tid & 1) * 4;       // 0 or 4
    const int am   = m0 + arow;
    const bool avalid = (am < NN);
    const float arcp = avalid ? g_rcp[am] : 0.f;
    // B-load mapping
    const int bkr = tid >> 5;             // 0..7
    const int bc  = (tid & 31) * 4;       // 0..124

    float acc[8][8];
#pragma unroll
    for (int i = 0; i < 8; i++)
#pragma unroll
        for (int j = 0; j < 8; j++) acc[i][j] = 0.f;

    // ---- fetch helpers inlined via lambdas ----
    auto fetchA = [&](int k0) -> float4 {
        float4 v = make_float4(0.f, 0.f, 0.f, 0.f);
        if (avalid) {
            int k = k0 + akq;
            if (k < DD) {
                v = *(const float4*)(g_agg + (size_t)am * DD + k);
                v.x *= arcp; v.y *= arcp; v.z *= arcp; v.w *= arcp;
            } else {
                v = __ldg((const float4*)(x + (size_t)am * DD + (k - DD)));
            }
        }
        return v;
    };
    auto fetchB = [&](int k0) -> float4 {
        return *(const float4*)(g_wt + (k0 + bkr) * DD + bc);
    };

    // preload stage 0
    {
        float4 pa = fetchA(0), pb = fetchB(0);
        As[0][akq + 0][arow] = pa.x;
        As[0][akq + 1][arow] = pa.y;
        As[0][akq + 2][arow] = pa.z;
        As[0][akq + 3][arow] = pa.w;
        *(float4*)&Bs[0][bkr][bc] = pb;
    }
    __syncthreads();

    int s = 0;
    for (int k0 = 0; k0 < KK; k0 += BK) {
        float4 pa, pb;
        const bool more = (k0 + BK < KK);
        if (more) { pa = fetchA(k0 + BK); pb = fetchB(k0 + BK); }

#pragma unroll
        for (int kk = 0; kk < BK; kk++) {
            float4 a0 = *(const float4*)&As[s][kk][ty * 8];
            float4 a1 = *(const float4*)&As[s][kk][ty * 8 + 4];
            float4 b0 = *(const float4*)&Bs[s][kk][tx * 8];
            float4 b1 = *(const float4*)&Bs[s][kk][tx * 8 + 4];
            float av[8] = {a0.x, a0.y, a0.z, a0.w, a1.x, a1.y, a1.z, a1.w};
            float bv[8] = {b0.x, b0.y, b0.z, b0.w, b1.x, b1.y, b1.z, b1.w};
#pragma unroll
            for (int i = 0; i < 8; i++)
#pragma unroll
                for (int j = 0; j < 8; j++)
                    acc[i][j] = fmaf(av[i], bv[j], acc[i][j]);
        }

        if (more) {
            int ns = s ^ 1;
            As[ns][akq + 0][arow] = pa.x;
            As[ns][akq + 1][arow] = pa.y;
            As[ns][akq + 2][arow] = pa.z;
            As[ns][akq + 3][arow] = pa.w;
            *(float4*)&Bs[ns][bkr][bc] = pb;
            __syncthreads();
            s = ns;
        }
    }

    // Epilogue: + bias, store h (pre-relu)
    float4 bb0 = __ldg((const float4*)b1l + tx * 2);
    float4 bb1 = __ldg((const float4*)b1l + tx * 2 + 1);
#pragma unroll
    for (int i = 0; i < 8; i++) {
        int m = m0 + ty * 8 + i;
        if (m < NN) {
            float4 o0 = make_float4(acc[i][0] + bb0.x, acc[i][1] + bb0.y,
                                    acc[i][2] + bb0.z, acc[i][3] + bb0.w);
            float4 o1 = make_float4(acc[i][4] + bb1.x, acc[i][5] + bb1.y,
                                    acc[i][6] + bb1.z, acc[i][7] + bb1.w);
            float* op = outh + (size_t)m * DD + tx * 8;
            *(float4*)op       = o0;
            *(float4*)(op + 4) = o1;
        }
    }
}

// ---------------------------------------------------------------------------
// Layer-2 projection: one warp per row.
//   s_l = relu(h)·w2_l,  pre = relu(h)·w2_r + b2
__global__ void __launch_bounds__(256) proj_kernel(
    const float* __restrict__ outh,
    const float* __restrict__ w2l, const float* __restrict__ b2l,
    const float* __restrict__ w2r) {
    unsigned tid  = blockIdx.x * 256u + threadIdx.x;
    unsigned row  = tid >> 5;
    if (row >= NN) return;
    unsigned lane = tid & 31;
    float4 h  = __ldg((const float4*)(outh + (size_t)row * DD) + lane);
    float4 wl = __ldg((const float4*)w2l + lane);
    float4 wr = __ldg((const float4*)w2r + lane);
    float r0 = fmaxf(h.x, 0.f), r1 = fmaxf(h.y, 0.f);
    float r2 = fmaxf(h.z, 0.f), r3 = fmaxf(h.w, 0.f);
    float sl = r0 * wl.x + r1 * wl.y + r2 * wl.z + r3 * wl.w;
    float sr = r0 * wr.x + r1 * wr.y + r2 * wr.z + r3 * wr.w;
#pragma unroll
    for (int off = 16; off > 0; off >>= 1) {
        sl += __shfl_xor_sync(0xffffffffu, sl, off);
        sr += __shfl_xor_sync(0xffffffffu, sr, off);
    }
    if (lane == 0) { g_sl[row] = sl; g_pre[row] = sr + __ldg(b2l); }
}

// ---------------------------------------------------------------------------
// Layer-2 aggregation collapsed to scalars: 1 float per edge.
__global__ void edge_agg2_kernel(const int* __restrict__ e32,
                                 const long long* __restrict__ e64) {
    unsigned e = blockIdx.x * 256u + threadIdx.x;
    if (e >= NE) return;
    int src, dst;
    if (g_is64) {
        src = (int)__ldg(&e64[e]);
        dst = (int)__ldg(&e64[NE + e]);
    } else {
        src = __ldg(&e32[e]);
        dst = __ldg(&e32[NE + e]);
    }
    atomicAdd(&g_t[dst], g_sl[src]);
}

__global__ void final_kernel(float* __restrict__ out0) {
    int i = blockIdx.x * 256 + threadIdx.x;
    if (i < NN) {
        float v = g_t[i] * g_rcp[i] + g_pre[i];
        out0[i] = 1.f / (1.f + expf(-v));
    }
}

// ---------------------------------------------------------------------------
extern "C" void kernel_launch(void* const* d_in, const int* in_sizes, int n_in,
                              void* d_out, int out_size) {
    const float*     x   = (const float*)d_in[0];
    const int*       e32 = (const int*)d_in[1];
    const long long* e64 = (const long long*)d_in[1];
    const float*     w1l = (const float*)d_in[2];
    const float*     b1l = (const float*)d_in[3];
    const float*     w1r = (const float*)d_in[4];
    const float*     w2l = (const float*)d_in[5];
    const float*     b2l = (const float*)d_in[6];
    const float*     w2r = (const float*)d_in[7];
    float* out0 = (float*)d_out;       // out [N,1]
    float* outh = out0 + NN;           // h   [N,128]

    detect_kernel<<<1, 32>>>(e32);
    zero_kernel<<<(NN * DD) / 256, 256>>>();
    trans_kernel<<<(KK * DD) / 256, 256>>>(w1l, w1r);
    edge_agg1_kernel<<<(NE * 32) / 256, 256>>>(e32, e64, x);
    rcp_kernel<<<(NN + 255) / 256, 256>>>();
    sage1_kernel<<<(NN + BM - 1) / BM, 256>>>(x, b1l, outh);
    proj_kernel<<<(NN * 32 + 255) / 256, 256>>>(outh, w2l, b2l, w2r);
    edge_agg2_kernel<<<(NE + 255) / 256, 256>>>(e32, e64);
    final_kernel<<<(NN + 255) / 256, 256>>>(out0);
}

// round 3
// speedup vs baseline: 2.4008x; 1.4862x over previous
#include <cuda_runtime.h>
#include <math.h>

#define NN 100000
#define NE 1600000
#define DD 128
#define KK 256      // concat(mean, x) inner dim
#define BM 128
#define BK 8
#define NB 391      // ceil(NN/256) blocks for the scan

// Scratch (device globals — no allocation allowed)
__device__ float g_agg[(size_t)NN * DD];   // mean-aggregated features, 51.2 MB
__device__ float g_rcp[NN];
__device__ float g_sl[NN];
__device__ float g_pre[NN];
__device__ float g_wt[KK * DD];            // transposed [k][n] weights
__device__ int   g_cnt[NN];
__device__ int   g_off[NN];
__device__ int   g_cur[NN];
__device__ int   g_esrc[NE];               // CSR: src indices sorted by dst
__device__ int   g_partial[512];
__device__ int   g_pinc[512];
__device__ int   g_is64;

// ---------------------------------------------------------------------------
// Detect edge_index dtype (int32 vs int64): for int64 < 2^31 every odd 32-bit
// word is 0; 16 consecutive zeros in random int32 data has prob ~1e-80.
__global__ void detect_kernel(const int* __restrict__ e) {
    if (threadIdx.x == 0) {
        int z = 0;
#pragma unroll
        for (int i = 1; i < 32; i += 2) z |= e[i];
        g_is64 = (z == 0) ? 1 : 0;
    }
}

__global__ void zero_cnt_kernel() {
    int i = blockIdx.x * 256 + threadIdx.x;
    if (i < NN) g_cnt[i] = 0;
}

// Histogram of dst degrees.
__global__ void hist_kernel(const int* __restrict__ e32,
                            const long long* __restrict__ e64) {
    unsigned e = blockIdx.x * 256u + threadIdx.x;
    if (e >= NE) return;
    int dst = g_is64 ? (int)__ldg(&e64[NE + e]) : __ldg(&e32[NE + e]);
    atomicAdd(&g_cnt[dst], 1);
}

// Per-256-block sums of g_cnt.
__global__ void block_sum_kernel() {
    __shared__ int s[256];
    int b = blockIdx.x, t = threadIdx.x;
    int i = b * 256 + t;
    s[t] = (i < NN) ? g_cnt[i] : 0;
    __syncthreads();
#pragma unroll
    for (int off = 128; off > 0; off >>= 1) {
        if (t < off) s[t] += s[t + off];
        __syncthreads();
    }
    if (t == 0) g_partial[b] = s[0];
}

// Inclusive scan of the NB partials (one block).
__global__ void scan_partial_kernel() {
    __shared__ int s[512];
    int t = threadIdx.x;
    s[t] = (t < NB) ? g_partial[t] : 0;
    __syncthreads();
#pragma unroll
    for (int off = 1; off < 512; off <<= 1) {
        int v = (t >= off) ? s[t - off] : 0;
        __syncthreads();
        s[t] += v;
        __syncthreads();
    }
    if (t < NB) g_pinc[t] = s[t];
}

// Per-block inclusive scan + base -> exclusive offsets; also rcp and cursor.
__global__ void block_scan_kernel() {
    __shared__ int s[256];
    int b = blockIdx.x, t = threadIdx.x;
    int i = b * 256 + t;
    int c = (i < NN) ? g_cnt[i] : 0;
    s[t] = c;
    __syncthreads();
#pragma unroll
    for (int off = 1; off < 256; off <<= 1) {
        int v = (t >= off) ? s[t - off] : 0;
        __syncthreads();
        s[t] += v;
        __syncthreads();
    }
    if (i < NN) {
        int base = (b > 0) ? g_pinc[b - 1] : 0;
        int excl = base + s[t] - c;
        g_off[i] = excl;
        g_cur[i] = excl;
        g_rcp[i] = 1.f / fmaxf((float)c, 1.f);
    }
}

// Scatter src into CSR order.
__global__ void scatter_kernel(const int* __restrict__ e32,
                               const long long* __restrict__ e64) {
    unsigned e = blockIdx.x * 256u + threadIdx.x;
    if (e >= NE) return;
    int src, dst;
    if (g_is64) {
        src = (int)__ldg(&e64[e]);
        dst = (int)__ldg(&e64[NE + e]);
    } else {
        src = __ldg(&e32[e]);
        dst = __ldg(&e32[NE + e]);
    }
    int pos = atomicAdd(&g_cur[dst], 1);
    g_esrc[pos] = src;
}

// Transpose+concat weights: g_wt[k][n] = (k<128 ? w1l[n][k] : w1r[n][k-128])
__global__ void trans_kernel(const float* __restrict__ w1l,
                             const float* __restrict__ w1r) {
    int idx = blockIdx.x * 256 + threadIdx.x;      // 0 .. 32767
    if (idx < KK * DD) {
        int k = idx >> 7, n = idx & 127;
        g_wt[idx] = (k < DD) ? w1l[n * DD + k] : w1r[n * DD + (k - DD)];
    }
}

// ---------------------------------------------------------------------------
// Gather-style mean aggregation: one warp per node, neighbors from CSR.
// Each lane owns 4 contiguous floats (float4) of the 128-wide row.
__global__ void __launch_bounds__(256) agg_kernel(const float* __restrict__ x) {
    unsigned tid  = blockIdx.x * 256u + threadIdx.x;
    unsigned row  = tid >> 5;
    if (row >= NN) return;
    unsigned lane = tid & 31;
    int beg = g_off[row];
    int end = beg + g_cnt[row];
    float4 a0 = make_float4(0.f, 0.f, 0.f, 0.f);
    float4 a1 = make_float4(0.f, 0.f, 0.f, 0.f);
    int e = beg;
    for (; e + 1 < end; e += 2) {
        int s0 = __ldg(&g_esrc[e]);
        int s1 = __ldg(&g_esrc[e + 1]);
        float4 v0 = __ldg((const float4*)(x + (size_t)s0 * DD) + lane);
        float4 v1 = __ldg((const float4*)(x + (size_t)s1 * DD) + lane);
        a0.x += v0.x; a0.y += v0.y; a0.z += v0.z; a0.w += v0.w;
        a1.x += v1.x; a1.y += v1.y; a1.z += v1.z; a1.w += v1.w;
    }
    if (e < end) {
        int s0 = __ldg(&g_esrc[e]);
        float4 v0 = __ldg((const float4*)(x + (size_t)s0 * DD) + lane);
        a0.x += v0.x; a0.y += v0.y; a0.z += v0.z; a0.w += v0.w;
    }
    float r = g_rcp[row];
    float4 m = make_float4((a0.x + a1.x) * r, (a0.y + a1.y) * r,
                           (a0.z + a1.z) * r, (a0.w + a1.w) * r);
    *((float4*)(g_agg + (size_t)row * DD) + lane) = m;
}

// ---------------------------------------------------------------------------
// Layer-1 GEMM: h = [mean | x] (100k x 256) @ g_wt (256 x 128) + b1.
// Double-buffered SGEMM: BM=128, BN=128, BK=8, 256 thr, 8x8 microtile.
__global__ void __launch_bounds__(256, 2) sage1_kernel(
    const float* __restrict__ x, const float* __restrict__ b1l,
    float* __restrict__ outh) {
    __shared__ float As[2][BK][BM];
    __shared__ float Bs[2][BK][DD];

    const int tid = threadIdx.x;
    const int m0  = blockIdx.x * BM;
    const int tx  = tid & 15, ty = tid >> 4;

    const int arow = tid >> 1;
    const int akq  = (tid & 1) * 4;
    const int am   = m0 + arow;
    const bool avalid = (am < NN);
    const int bkr = tid >> 5;
    const int bc  = (tid & 31) * 4;

    float acc[8][8];
#pragma unroll
    for (int i = 0; i < 8; i++)
#pragma unroll
        for (int j = 0; j < 8; j++) acc[i][j] = 0.f;

    auto fetchA = [&](int k0) -> float4 {
        float4 v = make_float4(0.f, 0.f, 0.f, 0.f);
        if (avalid) {
            int k = k0 + akq;
            if (k < DD)
                v = *(const float4*)(g_agg + (size_t)am * DD + k);
            else
                v = __ldg((const float4*)(x + (size_t)am * DD + (k - DD)));
        }
        return v;
    };
    auto fetchB = [&](int k0) -> float4 {
        return *(const float4*)(g_wt + (k0 + bkr) * DD + bc);
    };

    {
        float4 pa = fetchA(0), pb = fetchB(0);
        As[0][akq + 0][arow] = pa.x;
        As[0][akq + 1][arow] = pa.y;
        As[0][akq + 2][arow] = pa.z;
        As[0][akq + 3][arow] = pa.w;
        *(float4*)&Bs[0][bkr][bc] = pb;
    }
    __syncthreads();

    int s = 0;
    for (int k0 = 0; k0 < KK; k0 += BK) {
        float4 pa, pb;
        const bool more = (k0 + BK < KK);
        if (more) { pa = fetchA(k0 + BK); pb = fetchB(k0 + BK); }

#pragma unroll
        for (int kk = 0; kk < BK; kk++) {
            float4 a0 = *(const float4*)&As[s][kk][ty * 8];
            float4 a1 = *(const float4*)&As[s][kk][ty * 8 + 4];
            float4 b0 = *(const float4*)&Bs[s][kk][tx * 8];
            float4 b1 = *(const float4*)&Bs[s][kk][tx * 8 + 4];
            float av[8] = {a0.x, a0.y, a0.z, a0.w, a1.x, a1.y, a1.z, a1.w};
            float bv[8] = {b0.x, b0.y, b0.z, b0.w, b1.x, b1.y, b1.z, b1.w};
#pragma unroll
            for (int i = 0; i < 8; i++)
#pragma unroll
                for (int j = 0; j < 8; j++)
                    acc[i][j] = fmaf(av[i], bv[j], acc[i][j]);
        }

        if (more) {
            int ns = s ^ 1;
            As[ns][akq + 0][arow] = pa.x;
            As[ns][akq + 1][arow] = pa.y;
            As[ns][akq + 2][arow] = pa.z;
            As[ns][akq + 3][arow] = pa.w;
            *(float4*)&Bs[ns][bkr][bc] = pb;
            __syncthreads();
            s = ns;
        }
    }

    float4 bb0 = __ldg((const float4*)b1l + tx * 2);
    float4 bb1 = __ldg((const float4*)b1l + tx * 2 + 1);
#pragma unroll
    for (int i = 0; i < 8; i++) {
        int m = m0 + ty * 8 + i;
        if (m < NN) {
            float4 o0 = make_float4(acc[i][0] + bb0.x, acc[i][1] + bb0.y,
                                    acc[i][2] + bb0.z, acc[i][3] + bb0.w);
            float4 o1 = make_float4(acc[i][4] + bb1.x, acc[i][5] + bb1.y,
                                    acc[i][6] + bb1.z, acc[i][7] + bb1.w);
            float* op = outh + (size_t)m * DD + tx * 8;
            *(float4*)op       = o0;
            *(float4*)(op + 4) = o1;
        }
    }
}

// ---------------------------------------------------------------------------
// Layer-2 projection: one warp per row.
//   s_l = relu(h)·w2_l,  pre = relu(h)·w2_r + b2
__global__ void __launch_bounds__(256) proj_kernel(
    const float* __restrict__ outh,
    const float* __restrict__ w2l, const float* __restrict__ b2l,
    const float* __restrict__ w2r) {
    unsigned tid  = blockIdx.x * 256u + threadIdx.x;
    unsigned row  = tid >> 5;
    if (row >= NN) return;
    unsigned lane = tid & 31;
    float4 h  = __ldg((const float4*)(outh + (size_t)row * DD) + lane);
    float4 wl = __ldg((const float4*)w2l + lane);
    float4 wr = __ldg((const float4*)w2r + lane);
    float r0 = fmaxf(h.x, 0.f), r1 = fmaxf(h.y, 0.f);
    float r2 = fmaxf(h.z, 0.f), r3 = fmaxf(h.w, 0.f);
    float sl = r0 * wl.x + r1 * wl.y + r2 * wl.z + r3 * wl.w;
    float sr = r0 * wr.x + r1 * wr.y + r2 * wr.z + r3 * wr.w;
#pragma unroll
    for (int off = 16; off > 0; off >>= 1) {
        sl += __shfl_xor_sync(0xffffffffu, sl, off);
        sr += __shfl_xor_sync(0xffffffffu, sr, off);
    }
    if (lane == 0) { g_sl[row] = sl; g_pre[row] = sr + __ldg(b2l); }
}

// ---------------------------------------------------------------------------
// Layer-2 aggregation (CSR gather) + sigmoid, fused. Thread per node.
__global__ void final_kernel(float* __restrict__ out0) {
    int i = blockIdx.x * 256 + threadIdx.x;
    if (i >= NN) return;
    int beg = g_off[i];
    int end = beg + g_cnt[i];
    float t = 0.f;
    for (int e = beg; e < end; e++) t += __ldg(&g_sl[__ldg(&g_esrc[e])]);
    float v = t * g_rcp[i] + g_pre[i];
    out0[i] = 1.f / (1.f + expf(-v));
}

// ---------------------------------------------------------------------------
extern "C" void kernel_launch(void* const* d_in, const int* in_sizes, int n_in,
                              void* d_out, int out_size) {
    const float*     x   = (const float*)d_in[0];
    const int*       e32 = (const int*)d_in[1];
    const long long* e64 = (const long long*)d_in[1];
    const float*     w1l = (const float*)d_in[2];
    const float*     b1l = (const float*)d_in[3];
    const float*     w1r = (const float*)d_in[4];
    const float*     w2l = (const float*)d_in[5];
    const float*     b2l = (const float*)d_in[6];
    const float*     w2r = (const float*)d_in[7];
    float* out0 = (float*)d_out;       // out [N,1]
    float* outh = out0 + NN;           // h   [N,128]

    detect_kernel<<<1, 32>>>(e32);
    zero_cnt_kernel<<<NB, 256>>>();
    hist_kernel<<<(NE + 255) / 256, 256>>>(e32, e64);
    block_sum_kernel<<<NB, 256>>>();
    scan_partial_kernel<<<1, 512>>>();
    block_scan_kernel<<<NB, 256>>>();
    scatter_kernel<<<(NE + 255) / 256, 256>>>(e32, e64);
    trans_kernel<<<(KK * DD) / 256, 256>>>(w1l, w1r);
    agg_kernel<<<(NN * 32 + 255) / 256, 256>>>(x);
    sage1_kernel<<<(NN + BM - 1) / BM, 256>>>(x, b1l, outh);
    proj_kernel<<<(NN * 32 + 255) / 256, 256>>>(outh, w2l, b2l, w2r);
    final_kernel<<<(NN + 255) / 256, 256>>>(out0);
}